// round 1
// baseline (speedup 1.0000x reference)
#include <cuda_runtime.h>

// ShortConv: fused RMSNorm (over D) -> depthwise causal conv1d (K=4, over L) -> SiLU
// Shapes: x (B=4, L=4096, D=2048) fp32; norm_weight (D); conv_weight (K,1,D).
// Strategy: single pass, one HBM read + one HBM write per element.
//   grid: B * (L / ROWS) CTAs, each CTA owns ROWS contiguous L-rows of one batch.
//   block: 512 threads, thread t owns channels [4t, 4t+4) as a float4.
//   per row: load float4, block-reduce sum-of-squares -> rinv, normalize in regs,
//   conv uses rolling window of 3 previous normalized rows held in registers.

#define B_ 4
#define L_ 4096
#define D_ 2048
#define K_ 4

constexpr float EPS_ = 1e-5f;
constexpr int THREADS = 512;        // 512 * 4 = D
constexpr int ROWS = 32;            // L-rows per CTA
constexpr int CPB = L_ / ROWS;      // CTAs per batch = 128
constexpr int NWARPS = THREADS / 32;

__device__ __forceinline__ float4 f4_scale(float4 a, float s) {
    return make_float4(a.x * s, a.y * s, a.z * s, a.w * s);
}

__global__ __launch_bounds__(THREADS, 1)
void shortconv_kernel(const float* __restrict__ x,
                      const float* __restrict__ norm_w,
                      const float* __restrict__ conv_w,
                      float* __restrict__ out)
{
    const int b  = blockIdx.x / CPB;
    const int l0 = (blockIdx.x % CPB) * ROWS;
    const int t  = threadIdx.x;
    const int d  = t << 2;

    __shared__ float s_warp[NWARPS];
    __shared__ float s_rinv;

    // Load per-channel weights once; fold norm_weight into conv taps:
    //   y[l,d] = sum_k conv_w[k,d] * (x[l-3+k,d] * rinv[l-3+k] * norm_w[d])
    //          = sum_k (conv_w[k,d]*norm_w[d]) * x[l-3+k,d] * rinv[l-3+k]
    const float4 g  = *reinterpret_cast<const float4*>(norm_w + d);
    float4 w0 = *reinterpret_cast<const float4*>(conv_w + 0 * D_ + d);
    float4 w1 = *reinterpret_cast<const float4*>(conv_w + 1 * D_ + d);
    float4 w2 = *reinterpret_cast<const float4*>(conv_w + 2 * D_ + d);
    float4 w3 = *reinterpret_cast<const float4*>(conv_w + 3 * D_ + d);
    w0.x *= g.x; w0.y *= g.y; w0.z *= g.z; w0.w *= g.w;
    w1.x *= g.x; w1.y *= g.y; w1.z *= g.z; w1.w *= g.w;
    w2.x *= g.x; w2.y *= g.y; w2.z *= g.z; w2.w *= g.w;
    w3.x *= g.x; w3.y *= g.y; w3.z *= g.z; w3.w *= g.w;

    const float* xb = x   + (size_t)b * L_ * D_;
    float*       ob = out + (size_t)b * L_ * D_;

    // Rolling window of normalized rows: h0 = xn[l-3], h1 = xn[l-2], h2 = xn[l-1].
    float4 h0 = make_float4(0.f, 0.f, 0.f, 0.f);
    float4 h1 = h0, h2 = h0;

    // Warmup halo (rows l0-3..l0-1) unless at a batch start (causal zero pad).
    const int warm = (l0 == 0) ? 0 : 3;
    const int rbeg = l0 - warm;
    const int rend = l0 + ROWS;

    // Software-pipeline the row loads: issue next row's LDG before the
    // reduction barriers of the current row.
    float4 xc = *reinterpret_cast<const float4*>(xb + (size_t)rbeg * D_ + d);

    for (int r = rbeg; r < rend; ++r) {
        float4 xnext = make_float4(0.f, 0.f, 0.f, 0.f);
        if (r + 1 < rend)
            xnext = *reinterpret_cast<const float4*>(xb + (size_t)(r + 1) * D_ + d);

        // ---- block reduction of sum(x^2) over D ----
        float s = xc.x * xc.x + xc.y * xc.y + xc.z * xc.z + xc.w * xc.w;
        #pragma unroll
        for (int o = 16; o; o >>= 1)
            s += __shfl_xor_sync(0xffffffffu, s, o);
        if ((t & 31) == 0) s_warp[t >> 5] = s;
        __syncthreads();
        if (t < NWARPS) {
            float v = s_warp[t];
            #pragma unroll
            for (int o = NWARPS / 2; o; o >>= 1)
                v += __shfl_xor_sync(0x0000ffffu, v, o);
            if (t == 0) s_rinv = rsqrtf(v * (1.0f / D_) + EPS_);
        }
        __syncthreads();
        const float rinv = s_rinv;

        const float4 xn = f4_scale(xc, rinv);

        if (r >= l0) {
            float4 y;
            y.x = w0.x * h0.x + w1.x * h1.x + w2.x * h2.x + w3.x * xn.x;
            y.y = w0.y * h0.y + w1.y * h1.y + w2.y * h2.y + w3.y * xn.y;
            y.z = w0.z * h0.z + w1.z * h1.z + w2.z * h2.z + w3.z * xn.z;
            y.w = w0.w * h0.w + w1.w * h1.w + w2.w * h2.w + w3.w * xn.w;
            // SiLU: y * sigmoid(y)
            y.x = y.x / (1.0f + __expf(-y.x));
            y.y = y.y / (1.0f + __expf(-y.y));
            y.z = y.z / (1.0f + __expf(-y.z));
            y.w = y.w / (1.0f + __expf(-y.w));
            *reinterpret_cast<float4*>(ob + (size_t)r * D_ + d) = y;
        }

        h0 = h1; h1 = h2; h2 = xn;
        xc = xnext;
    }
}

extern "C" void kernel_launch(void* const* d_in, const int* in_sizes, int n_in,
                              void* d_out, int out_size)
{
    const float* x  = nullptr;
    const float* nw = nullptr;
    const float* cw = nullptr;
    for (int i = 0; i < n_in; ++i) {
        if      (in_sizes[i] == B_ * L_ * D_) x  = (const float*)d_in[i];
        else if (in_sizes[i] == D_)           nw = (const float*)d_in[i];
        else if (in_sizes[i] == K_ * D_)      cw = (const float*)d_in[i];
    }
    shortconv_kernel<<<B_ * CPB, THREADS>>>(x, nw, cw, (float*)d_out);
}